// round 14
// baseline (speedup 1.0000x reference)
#include <cuda_runtime.h>
#include <cstdint>

// EMA scan: y_t = d*x_t + (1-d)*y_{t-1}, y_{-1} = x[0], d = 0.9 (a = 0.1).
//
// Persistent warps, BLOCKED segment assignment:
//  - Each warp owns a contiguous span of 512-element chunks (4 rows x 32
//    lanes x float4). The carry leaving chunk j (lane-31 inclusive scan
//    value, already computed) seeds chunk j+1 directly -> the per-segment
//    gmem halo load + halo scan + seed branch are gone; each warp does one
//    halo scan total, at its span start.
//  - Register double-buffer: chunk j+1's loads issue before chunk j's
//    compute (latency hiding, zero smem, zero barriers).
//  - Lookback 16 elements (a^16 = 1e-16 << fp32 eps): Kogge-Stone {1,2};
//    per-lane carry factor truncated to 0 for lane >= 4.
//  - Stores __stcs (streaming, best in A/B); loads plain __ldg.

#define NT    256
#define NW    (NT / 32)
#define ROWS  4
#define ROWE  128                 // elements per row
#define WREG  (ROWS * ROWE)       // 512 elements per chunk

__device__ __forceinline__ float horner4(float a, float4 w) {
    float h = w.x;
    h = fmaf(a, h, w.y);
    h = fmaf(a, h, w.z);
    h = fmaf(a, h, w.w);
    return h;
}

__device__ __forceinline__ void load_chunk(const float* __restrict__ x, int n,
                                           int wbase, int lane, float4 v[ROWS])
{
    if (wbase + WREG <= n) {
        #pragma unroll
        for (int r = 0; r < ROWS; r++)
            v[r] = *reinterpret_cast<const float4*>(
                       x + wbase + r * ROWE + 4 * lane);
    } else {
        #pragma unroll
        for (int r = 0; r < ROWS; r++) {
            int g = wbase + r * ROWE + 4 * lane;
            v[r].x = (g + 0 < n) ? x[g + 0] : 0.0f;
            v[r].y = (g + 1 < n) ? x[g + 1] : 0.0f;
            v[r].z = (g + 2 < n) ? x[g + 2] : 0.0f;
            v[r].w = (g + 3 < n) ? x[g + 3] : 0.0f;
        }
    }
}

__global__ __launch_bounds__(NT, 4)
void ema_kernel(const float* __restrict__ x,
                const float* __restrict__ decay_p,
                float* __restrict__ out, int n,
                int nchunk, int span)
{
    const float d  = __ldg(decay_p);
    const float a  = 1.0f - d;
    const float a2 = a * a;
    const float p4 = a2 * a2;
    const float p8 = p4 * p4;

    const int lane = threadIdx.x & 31;
    const int wid  = threadIdx.x >> 5;

    // per-lane carry factor a^(4*lane), truncated to 0 for lane >= 4
    float f = 0.0f;
    if (lane < 4)
        f = ((lane & 1) ? p4 : 1.0f) * ((lane & 2) ? p8 : 1.0f);

    const int gw = blockIdx.x * NW + wid;       // global warp id
    const int c0 = gw * span;
    if (c0 >= nchunk) return;
    const int c1 = min(c0 + span, nchunk);

    int wbase = c0 * WREG;

    // ---- one-time warp seed at span start ----
    float cw;
    if (wbase == 0) {
        cw = __ldg(x);                          // exact: y_{-1} = x[0]
    } else {
        float hS = 0.0f;
        if (lane < 4) {
            const float4 hv = *reinterpret_cast<const float4*>(
                x + wbase - 16 + 4 * lane);
            float4 w = make_float4(d * hv.x, d * hv.y, d * hv.z, d * hv.w);
            hS = horner4(a, w);
        }
        float m;
        m = __shfl_up_sync(0xffffffffu, hS, 1);
        if (lane >= 1) hS = fmaf(p4, m, hS);
        m = __shfl_up_sync(0xffffffffu, hS, 2);
        if (lane >= 2) hS = fmaf(p8, m, hS);
        cw = __shfl_sync(0xffffffffu, hS, 3);   // carry entering the span
    }

    // ---- pipelined blocked loop: carry flows in cw across chunks ----
    float4 vc[ROWS];
    load_chunk(x, n, wbase, lane, vc);

    for (int c = c0;;) {
        const bool have_next = (c + 1 < c1);
        float4 vn[ROWS];
        if (have_next)
            load_chunk(x, n, wbase + WREG, lane, vn);   // prefetch next chunk

        const bool full = (wbase + WREG <= n);

        #pragma unroll
        for (int r = 0; r < ROWS; r++) {
            float4 w = make_float4(d * vc[r].x, d * vc[r].y,
                                   d * vc[r].z, d * vc[r].w);
            float S = horner4(a, w);
            float t;
            t = __shfl_up_sync(0xffffffffu, S, 1);
            if (lane >= 1) S = fmaf(p4, t, S);
            t = __shfl_up_sync(0xffffffffu, S, 2);
            if (lane >= 2) S = fmaf(p8, t, S);
            // S covers lanes r-3..r (16 elements) — full required lookback.

            float E = __shfl_up_sync(0xffffffffu, S, 1);
            if (lane == 0) E = 0.0f;
            float c2 = fmaf(f, cw, E);          // carry entering own 4 elems

            float y0 = fmaf(a, c2, w.x);
            float y1 = fmaf(a, y0, w.y);
            float y2 = fmaf(a, y1, w.z);
            float y3 = fmaf(a, y2, w.w);

            cw = __shfl_sync(0xffffffffu, S, 31);   // carry to next row/chunk

            int g = wbase + r * ROWE + 4 * lane;
            if (full) {
                __stcs(reinterpret_cast<float4*>(out + g),
                       make_float4(y0, y1, y2, y3));
            } else {
                if (g + 0 < n) out[g + 0] = y0;
                if (g + 1 < n) out[g + 1] = y1;
                if (g + 2 < n) out[g + 2] = y2;
                if (g + 3 < n) out[g + 3] = y3;
            }
        }

        if (!have_next) break;
        #pragma unroll
        for (int r = 0; r < ROWS; r++) vc[r] = vn[r];
        wbase += WREG;
        c++;
    }
}

extern "C" void kernel_launch(void* const* d_in, const int* in_sizes, int n_in,
                              void* d_out, int out_size)
{
    const float* x     = (const float*)d_in[0];
    const float* decay = (const float*)d_in[1];
    float*       out   = (float*)d_out;
    const int    n     = in_sizes[0];

    const int nchunk = (n + WREG - 1) / WREG;        // 512-elem chunks
    int grid = 148 * 4;                              // persistent CTAs
    int wtot = grid * NW;
    if (wtot > nchunk) { grid = (nchunk + NW - 1) / NW; wtot = grid * NW; }
    const int span = (nchunk + wtot - 1) / wtot;     // chunks per warp

    ema_kernel<<<grid, NT>>>(x, decay, out, n, nchunk, span);
}

// round 15
// speedup vs baseline: 1.2003x; 1.2003x over previous
#include <cuda_runtime.h>
#include <cstdint>

// EMA scan: y_t = d*x_t + (1-d)*y_{t-1}, y_{-1} = x[0], d = 0.9 (a = 0.1).
//
// Proven R7/R9 structure (persistent software-pipelined warps, STRIDED
// segment mapping -> independent per-segment halo seeds, register double
// buffer, zero smem / zero barriers), with ROWS=5 (640-elem segments) to
// amortize per-segment fixed costs over 25% more bytes at the same
// 4-CTA/SM register envelope.
//  - Lookback 16 elements (a^16 = 1e-16 << fp32 eps): Kogge-Stone {1,2};
//    per-lane carry factor truncated to 0 for lane >= 4.
//  - Row carry_out = lane-31 inclusive value (independent of carry_in) ->
//    rows ILP-parallel inside a segment; segments independent across the
//    persistent loop (seed from gmem halo, not from previous segment).
//  - Stores __stcs (streaming; best in A/B). Loads via const __restrict.

#define NT    256
#define NW    (NT / 32)
#define ROWS  5
#define ROWE  128                 // elements per row
#define WREG  (ROWS * ROWE)       // 640 elements per warp-segment
#define TILE  (NW * WREG)         // 5120 elements per block-segment

__device__ __forceinline__ float horner4(float a, float4 w) {
    float h = w.x;
    h = fmaf(a, h, w.y);
    h = fmaf(a, h, w.z);
    h = fmaf(a, h, w.w);
    return h;
}

__device__ __forceinline__ void load_seg(const float* __restrict__ x, int n,
                                         int wbase, int lane,
                                         float4 v[ROWS], float4& hv)
{
    hv = make_float4(0.f, 0.f, 0.f, 0.f);
    if (wbase != 0 && wbase <= n && lane < 4)
        hv = *reinterpret_cast<const float4*>(x + wbase - 16 + 4 * lane);

    if (wbase + WREG <= n) {
        #pragma unroll
        for (int r = 0; r < ROWS; r++)
            v[r] = *reinterpret_cast<const float4*>(
                       x + wbase + r * ROWE + 4 * lane);
    } else {
        #pragma unroll
        for (int r = 0; r < ROWS; r++) {
            int g = wbase + r * ROWE + 4 * lane;
            v[r].x = (g + 0 < n) ? x[g + 0] : 0.0f;
            v[r].y = (g + 1 < n) ? x[g + 1] : 0.0f;
            v[r].z = (g + 2 < n) ? x[g + 2] : 0.0f;
            v[r].w = (g + 3 < n) ? x[g + 3] : 0.0f;
        }
    }
}

__device__ __forceinline__ void process_seg(const float* __restrict__ x,
                                            float* __restrict__ out, int n,
                                            int wbase, int lane,
                                            float d, float a, float p4, float p8,
                                            float f,
                                            const float4 v[ROWS], float4 hv)
{
    if (wbase >= n) return;

    // incoming warp carry from the 16-element halo (lanes 0-3 hold data)
    float cw;
    if (wbase == 0) {
        cw = __ldg(x);                          // exact: y_{-1} = x[0]
    } else {
        float hS = 0.0f;
        if (lane < 4) {
            float4 w = make_float4(d * hv.x, d * hv.y, d * hv.z, d * hv.w);
            hS = horner4(a, w);
        }
        float m;
        m = __shfl_up_sync(0xffffffffu, hS, 1);
        if (lane >= 1) hS = fmaf(p4, m, hS);
        m = __shfl_up_sync(0xffffffffu, hS, 2);
        if (lane >= 2) hS = fmaf(p8, m, hS);
        cw = __shfl_sync(0xffffffffu, hS, 3);
    }

    const bool full = (wbase + WREG <= n);

    #pragma unroll
    for (int r = 0; r < ROWS; r++) {
        float4 w = make_float4(d * v[r].x, d * v[r].y, d * v[r].z, d * v[r].w);
        float S = horner4(a, w);
        float t;
        t = __shfl_up_sync(0xffffffffu, S, 1);
        if (lane >= 1) S = fmaf(p4, t, S);
        t = __shfl_up_sync(0xffffffffu, S, 2);
        if (lane >= 2) S = fmaf(p8, t, S);
        // S covers lanes r-3..r (16 elements) — full required lookback.

        float E = __shfl_up_sync(0xffffffffu, S, 1);
        if (lane == 0) E = 0.0f;
        float c = fmaf(f, cw, E);               // carry entering own 4 elems

        float y0 = fmaf(a, c,  w.x);
        float y1 = fmaf(a, y0, w.y);
        float y2 = fmaf(a, y1, w.z);
        float y3 = fmaf(a, y2, w.w);

        cw = __shfl_sync(0xffffffffu, S, 31);   // carry_out (indep of carry_in)

        int g = wbase + r * ROWE + 4 * lane;
        if (full) {
            __stcs(reinterpret_cast<float4*>(out + g),
                   make_float4(y0, y1, y2, y3));
        } else {
            if (g + 0 < n) out[g + 0] = y0;
            if (g + 1 < n) out[g + 1] = y1;
            if (g + 2 < n) out[g + 2] = y2;
            if (g + 3 < n) out[g + 3] = y3;
        }
    }
}

__global__ __launch_bounds__(NT, 4)
void ema_kernel(const float* __restrict__ x,
                const float* __restrict__ decay_p,
                float* __restrict__ out, int n, int nseg)
{
    const float d  = __ldg(decay_p);
    const float a  = 1.0f - d;
    const float a2 = a * a;
    const float p4 = a2 * a2;
    const float p8 = p4 * p4;

    const int lane   = threadIdx.x & 31;
    const int wid    = threadIdx.x >> 5;
    const int stride = gridDim.x;

    // per-lane carry factor a^(4*lane), truncated to 0 for lane >= 4
    float f = 0.0f;
    if (lane < 4)
        f = ((lane & 1) ? p4 : 1.0f) * ((lane & 2) ? p8 : 1.0f);

    int seg = blockIdx.x;
    if (seg >= nseg) return;

    int wbase = seg * TILE + wid * WREG;
    float4 vc[ROWS], hc;
    load_seg(x, n, wbase, lane, vc, hc);

    for (;;) {
        const int seg2 = seg + stride;
        const bool have_next = (seg2 < nseg);

        float4 vn[ROWS], hn;
        const int wbase2 = seg2 * TILE + wid * WREG;
        if (have_next)
            load_seg(x, n, wbase2, lane, vn, hn);   // prefetch next segment

        process_seg(x, out, n, wbase, lane, d, a, p4, p8, f, vc, hc);

        if (!have_next) break;
        #pragma unroll
        for (int r = 0; r < ROWS; r++) vc[r] = vn[r];
        hc = hn;
        wbase = wbase2;
        seg = seg2;
    }
}

extern "C" void kernel_launch(void* const* d_in, const int* in_sizes, int n_in,
                              void* d_out, int out_size)
{
    const float* x     = (const float*)d_in[0];
    const float* decay = (const float*)d_in[1];
    float*       out   = (float*)d_out;
    const int    n     = in_sizes[0];

    const int nseg = (n + TILE - 1) / TILE;
    int grid = 148 * 4;                 // persistent: 4 CTAs/SM on 148 SMs
    if (grid > nseg) grid = nseg;
    ema_kernel<<<grid, NT>>>(x, decay, out, n, nseg);
}